// round 16
// baseline (speedup 1.0000x reference)
#include <cuda_runtime.h>
#include <cuda_fp16.h>
#include <cstdint>

#define SEQ 256
#define B_  32
#define TILE 4096   // 64*64 floats
#define NSTG 8

// LAYOUT L4 (verified): tile (b,t) at (t*32+b)*TILE; interior transposed:
// element (i,j) at offset j*64 + i.

__device__ float g_fv[32][64];
__device__ float g_bv[32][64];
__device__ float g_fo[32];
__device__ float g_bo[32];
__device__ float g_sc[32];
__device__ int   g_ct[32];
__device__ int   g_done;

__device__ __forceinline__ void cp16(unsigned int dst, const float* src) {
    asm volatile("cp.async.cg.shared.global [%0], [%1], 16;\n" :: "r"(dst), "l"(src));
}
__device__ __forceinline__ void cp_commit() { asm volatile("cp.async.commit_group;\n" ::: "memory"); }
__device__ __forceinline__ void cp_wait6()  { asm volatile("cp.async.wait_group 6;\n" ::: "memory"); }

__device__ __forceinline__ int swz_b(int c, int r) {   // bwd chunk swizzle
    return c ^ ((r & 7) ^ ((r >> 3) & 7));
}

__device__ __forceinline__ int bf16_ok(unsigned h) {
    const float g = __uint_as_float(h << 16);
    return (h == 0u) || (g >= 1.f && g < 64.f && g == floorf(g));
}
__device__ __forceinline__ int decode_tgt(const unsigned* tu, int mode, int e) {
    int v;
    if      (mode == 0) v = (int)tu[2 * e];
    else if (mode == 1) v = (int)tu[e];
    else if (mode == 2) v = (int)((tu[e >> 1] >> ((e & 1) * 16)) & 0xFFFFu);
    else if (mode == 3) v = (int)((tu[e >> 2] >> ((e & 3) * 8)) & 0xFFu);
    else if (mode == 4) v = (int)__uint_as_float(tu[e]);
    else if (mode == 5) v = (int)__uint_as_float(((tu[e >> 1] >> ((e & 1) * 16)) & 0xFFFFu) << 16);
    else                v = (int)__hiloint2double(tu[2 * e + 1], tu[2 * e]);
    return v & 63;
}

__device__ __forceinline__ float2 exp2f2(float2 e) {
    const float L2E = 1.4426950408889634f;
    return __half22float2(h2exp2(__floats2half2_rn(e.x * L2E, e.y * L2E)));
}
__device__ __forceinline__ float4 exp4f(float4 e) {
    const float L2E = 1.4426950408889634f;
    const float2 fa = __half22float2(h2exp2(__floats2half2_rn(e.x * L2E, e.y * L2E)));
    const float2 fb = __half22float2(h2exp2(__floats2half2_rn(e.z * L2E, e.w * L2E)));
    return make_float4(fa.x, fa.y, fb.x, fb.y);
}

// -------------------------------------------------------------------------
// grid = 64, 512 threads. Block blk: batch b = blk>>1, dir = blk&1.
// Warp w (0..15) owns 4 outputs; lane owns summed-pair {2lane, 2lane+1}.
// fwd: outputs = stored rows (linear stage layout, row float2 reads).
// bwd: outputs = stored cols (chunk-swizzled stage, col-quad float4 reads).
// 5-stage shuffle butterfly; renorm by exact 2^-k every 8 steps.
// -------------------------------------------------------------------------
__global__ void __launch_bounds__(512) crf_fused(const float* __restrict__ emits,
                                                 const unsigned char* __restrict__ mask,
                                                 const unsigned* __restrict__ tu,
                                                 float* __restrict__ out)
{
    extern __shared__ float stage[];            // NSTG x 4096 floats
    __shared__ float sA[64];
    __shared__ float sMax[16];
    __shared__ unsigned char sM[256];
    __shared__ float sRed2[2];
    __shared__ float sv[16];
    __shared__ int   scnt[16];
    __shared__ double sAcc[16];
    __shared__ int   sCt2[16];

    const int blk = blockIdx.x;
    const int tid = threadIdx.x;
    const int b = blk >> 1, dir = blk & 1;
    const int w = tid >> 5, lane = tid & 31;

    const unsigned int stage_u32 = (unsigned int)__cvta_generic_to_shared(stage);

    // cp.async src/dst for this thread's 2 chunks per stage
    unsigned int cp_d[2];
    int cp_m[2];
    #pragma unroll
    for (int k = 0; k < 2; k++) {
        const int m = k * 512 + tid;
        const int row = m >> 4, c = m & 15;
        const int sw = dir ? swz_b(c, row) : c;
        cp_m[k] = m;
        cp_d[k] = (unsigned int)((row * 64 + sw * 4) * 4);
    }

    // bwd read offsets (float index)
    const int r0 = 2 * lane, r1 = r0 + 1;
    const int rd0 = r0 * 64 + swz_b(w, r0) * 4;
    const int rd1 = r1 * 64 + swz_b(w, r1) * 4;

    if (tid < 256) sM[tid] = mask[b * SEQ + tid];

    const int nsteps = dir ? 128 : 127;

    // prologue: 7 stages
    #pragma unroll
    for (int s = 0; s < NSTG - 1; s++) {
        const int t = dir ? 255 - s : 1 + s;
        const float* src = emits + (size_t)(t * B_ + b) * TILE;
        const unsigned int stg = stage_u32 + (unsigned int)s * 16384u;
        cp16(stg + cp_d[0], src + cp_m[0] * 4);
        cp16(stg + cp_d[1], src + cp_m[1] * 4);
        cp_commit();
    }

    // init alpha
    float m0 = 0.f;
    if (dir == 0) {
        float e0 = (tid < 64) ? emits[(size_t)b * TILE + tid * 64] : -1e30f;
        if (tid < 64) {
            float v = e0;
            #pragma unroll
            for (int o = 16; o; o >>= 1) v = fmaxf(v, __shfl_xor_sync(~0u, v, o));
            if ((tid & 31) == 0) sRed2[tid >> 5] = v;
        }
        __syncthreads();
        m0 = fmaxf(sRed2[0], sRed2[1]);
        if (tid < 64) sA[tid] = __expf(e0 - m0);
    } else {
        if (tid < 64) sA[tid] = 1.f;
    }

    int K = 0;
    for (int s = 0; s < nsteps; s++) {
        cp_wait6();
        __syncthreads();               // stage s ready; sA from prev step visible

        const float* st = stage + (s & (NSTG - 1)) * 4096;
        const float2 a2 = *(const float2*)&sA[2 * lane];
        const float4 aold = *(const float4*)&sA[4 * w];    // warp-uniform broadcast

        float4 acc;
        if (dir == 0) {
            const float2 x0 = *(const float2*)&st[(4 * w + 0) * 64 + 2 * lane];
            const float2 x1 = *(const float2*)&st[(4 * w + 1) * 64 + 2 * lane];
            const float2 x2 = *(const float2*)&st[(4 * w + 2) * 64 + 2 * lane];
            const float2 x3 = *(const float2*)&st[(4 * w + 3) * 64 + 2 * lane];
            const float2 e0 = exp2f2(x0), e1 = exp2f2(x1);
            const float2 e2 = exp2f2(x2), e3 = exp2f2(x3);
            acc.x = a2.x * e0.x + a2.y * e0.y;
            acc.y = a2.x * e1.x + a2.y * e1.y;
            acc.z = a2.x * e2.x + a2.y * e2.y;
            acc.w = a2.x * e3.x + a2.y * e3.y;
        } else {
            const float4 v0 = *(const float4*)&st[rd0];
            const float4 v1 = *(const float4*)&st[rd1];
            const float4 E0 = exp4f(v0);
            const float4 E1 = exp4f(v1);
            acc.x = a2.x * E0.x + a2.y * E1.x;
            acc.y = a2.x * E0.y + a2.y * E1.y;
            acc.z = a2.x * E0.z + a2.y * E1.z;
            acc.w = a2.x * E0.w + a2.y * E1.w;
        }

        // issue stage s+7 (off the dependency chain)
        {
            const int sp = s + NSTG - 1;
            if (sp < nsteps) {
                const int t = dir ? 255 - sp : 1 + sp;
                const float* src = emits + (size_t)(t * B_ + b) * TILE;
                const unsigned int stg = stage_u32 + (unsigned int)(sp & (NSTG - 1)) * 16384u;
                cp16(stg + cp_d[0], src + cp_m[0] * 4);
                cp16(stg + cp_d[1], src + cp_m[1] * 4);
            }
            cp_commit();
        }

        // 5-stage butterfly over the 32 summed-pairs
        #pragma unroll
        for (int o = 1; o <= 16; o <<= 1) {
            acc.x += __shfl_xor_sync(~0u, acc.x, o);
            acc.y += __shfl_xor_sync(~0u, acc.y, o);
            acc.z += __shfl_xor_sync(~0u, acc.z, o);
            acc.w += __shfl_xor_sync(~0u, acc.w, o);
        }

        const int t = dir ? 255 - s : 1 + s;
        const bool msk = sM[t] != 0;

        if ((s & 7) == 7) {   // renorm (uniform branch)
            const float m = fmaxf(fmaxf(acc.x, acc.y), fmaxf(acc.z, acc.w));
            if (lane == 0) sMax[w] = m;
            __syncthreads();
            const float4 x0 = *(const float4*)&sMax[0];
            const float4 x1 = *(const float4*)&sMax[4];
            const float4 x2 = *(const float4*)&sMax[8];
            const float4 x3 = *(const float4*)&sMax[12];
            float gm = fmaxf(fmaxf(fmaxf(x0.x, x0.y), fmaxf(x0.z, x0.w)),
                             fmaxf(fmaxf(x1.x, x1.y), fmaxf(x1.z, x1.w)));
            gm = fmaxf(gm, fmaxf(fmaxf(fmaxf(x2.x, x2.y), fmaxf(x2.z, x2.w)),
                                 fmaxf(fmaxf(x3.x, x3.y), fmaxf(x3.z, x3.w))));
            if (msk) {
                const int kx = ((__float_as_int(gm) >> 23) & 0xFF) - 127;   // ilogb
                const float scale = __int_as_float((127 - kx) << 23);       // exact 2^-kx
                K += kx;
                acc.x *= scale; acc.y *= scale; acc.z *= scale; acc.w *= scale;
            }
        }

        if (lane == 0) {
            float4 wv;
            wv.x = msk ? acc.x : aold.x;
            wv.y = msk ? acc.y : aold.y;
            wv.z = msk ? acc.z : aold.z;
            wv.w = msk ? acc.w : aold.w;
            *(float4*)&sA[4 * w] = wv;
        }
    }

    __syncthreads();
    if (tid < 64) {
        if (dir == 0) g_fv[b][tid] = sA[tid];
        else          g_bv[b][tid] = sA[tid];
    }
    if (tid == 0) {
        const float off = (float)K * 0.6931471805599453f + (dir ? 0.f : m0);
        if (dir == 0) g_fo[b] = off; else g_bo[b] = off;
    }

    // ---- dir==0 epilogue: path score for batch b ----
    if (dir == 0) {
        const int ti = tid & 255;                 // threads >=256 duplicate tests
        const unsigned wd = tu[ti];
        const unsigned h0 = wd & 0xFFFFu, h1 = wd >> 16;
        const float    f  = __uint_as_float(wd);
        int okA = (ti & 1) ? (wd == 0u) : (wd < 64u);
        int okB = (wd < 64u);
        int okI = (h0 < 64u) && (h1 < 64u);
        int okE = ((wd & 0xC0C0C0C0u) == 0u);
        int okC = (wd == 0u) || (f >= 1.f && f < 64.f && f == floorf(f));
        int okF = bf16_ok(h0) && bf16_ok(h1);
        okA = __syncthreads_and(okA);
        okB = __syncthreads_and(okB);
        okI = __syncthreads_and(okI);
        okE = __syncthreads_and(okE);
        okC = __syncthreads_and(okC);
        okF = __syncthreads_and(okF);
        const int mode = okA ? 0 : okB ? 1 : okI ? 2 : okE ? 3 : okC ? 4 : okF ? 5 : 6;

        float v = 0.f; int c = 0;
        if (tid < 256) {
            const int row = b * (SEQ + 1);
            const int i0 = decode_tgt(tu, mode, row + tid);
            const int i1 = decode_tgt(tu, mode, row + tid + 1);
            if (sM[tid]) {
                v = emits[(size_t)(tid * B_ + b) * TILE + i1 * 64 + i0];
                c = 1;
            }
        }
        #pragma unroll
        for (int o = 16; o; o >>= 1) {
            v += __shfl_xor_sync(~0u, v, o);
            c += __shfl_xor_sync(~0u, c, o);
        }
        if (lane == 0) { sv[w] = v; scnt[w] = c; }
        __syncthreads();
        if (tid == 0) {
            float tv = 0.f; int tc = 0;
            #pragma unroll
            for (int k = 0; k < 16; k++) { tv += sv[k]; tc += scnt[k]; }
            g_sc[b] = tv;
            g_ct[b] = tc;
        }
    }

    // ---- arrive; block 0 finishes the loss ----
    __threadfence();
    __syncthreads();
    if (tid == 0) atomicAdd(&g_done, 1);

    if (blk == 0) {
        if (tid == 0) {
            while (atomicAdd(&g_done, 0) < 64) __nanosleep(64);
            __threadfence();
        }
        __syncthreads();

        double accd = 0.0; int ctd = 0;
        for (int bb = w; bb < 32; bb += 16) {
            float part = g_fv[bb][lane] * g_bv[bb][lane]
                       + g_fv[bb][lane + 32] * g_bv[bb][lane + 32];
            #pragma unroll
            for (int o = 16; o; o >>= 1) part += __shfl_xor_sync(~0u, part, o);
            if (lane == 0) {
                accd += (double)(logf(part) + g_fo[bb] + g_bo[bb]) - (double)g_sc[bb];
                ctd  += g_ct[bb];
            }
        }
        if (lane == 0) { sAcc[w] = accd; sCt2[w] = ctd; }
        __syncthreads();
        if (tid == 0) {
            double sd = 0.0; int cd = 0;
            #pragma unroll
            for (int k = 0; k < 16; k++) { sd += sAcc[k]; cd += sCt2[k]; }
            out[0] = (float)(sd / (double)cd);
            __threadfence();
            g_done = 0;   // reset for next graph replay
        }
    }
}

extern "C" void kernel_launch(void* const* d_in, const int* in_sizes, int n_in,
                              void* d_out, int out_size)
{
    int ie = 0;
    for (int k = 1; k < n_in; k++) if (in_sizes[k] > in_sizes[ie]) ie = k;
    int im = -1, it = -1;
    for (int k = 0; k < n_in; k++) {
        if (k == ie) continue;
        if (in_sizes[k] == 8192 && im < 0) im = k; else it = k;
    }
    if (im < 0) { im = 2; }
    if (it < 0) { it = (im == 1) ? 2 : 1; }

    const float*         emits = (const float*)d_in[ie];
    const unsigned*      tg    = (const unsigned*)d_in[it];
    const unsigned char* mask  = (const unsigned char*)d_in[im];

    const int smem_bytes = NSTG * 4096 * 4;   // 131072
    cudaFuncSetAttribute(crf_fused, cudaFuncAttributeMaxDynamicSharedMemorySize, smem_bytes);

    crf_fused<<<64, 512, smem_bytes>>>(emits, mask, tg, (float*)d_out);
}